// round 2
// baseline (speedup 1.0000x reference)
#include <cuda_runtime.h>
#include <math.h>

#define B_I_DIM   512
#define B_O_DIM   32
#define B_J_DIM   9            // degree+1
#define B_IC      8            // i's per k-chunk
#define B_KC      (B_IC * B_J_DIM)   // 72
#define B_TB      128          // batch rows per CTA
#define B_THREADS 256
#define B_NCHUNK  (B_I_DIM / B_IC)   // 64
#define B_KTOT    (B_I_DIM * B_J_DIM) // 4608

// Repacked weights, k-major: g_W2[(i*9 + j)*32 + o] = W[i][o][j]
__device__ float g_W2[B_KTOT * B_O_DIM];

__global__ void repack_w_kernel(const float* __restrict__ w) {
    int f = blockIdx.x * blockDim.x + threadIdx.x;   // flat over i*o*j (gmem order)
    if (f >= B_I_DIM * B_O_DIM * B_J_DIM) return;
    int j = f % B_J_DIM;
    int o = (f / B_J_DIM) % B_O_DIM;
    int i = f / (B_J_DIM * B_O_DIM);
    g_W2[(i * B_J_DIM + j) * B_O_DIM + o] = w[f];
}

__global__ __launch_bounds__(B_THREADS)
void cheby_kan_kernel(const float* __restrict__ x, float* __restrict__ out) {
    __shared__ float Ts[B_KC][B_TB];     // basis values, k-major rows
    __shared__ float Ws[B_KC][B_O_DIM];  // weight chunk, k-major rows

    const int t   = threadIdx.x;
    const int b0  = blockIdx.x * B_TB;
    // fill-phase mapping: thread -> (row, half of 8 i's)
    const int row = t >> 1;            // 0..127
    const int ih  = (t & 1) * 4;       // 0 or 4
    // compute-phase mapping: 4 rows x 4 outputs per thread
    const int tx  = t & 7;             // output group -> cols tx*4..tx*4+3
    const int ty  = t >> 3;            // row group    -> rows ty*4..ty*4+3

    const float* xrow = x + (size_t)(b0 + row) * B_I_DIM;

    float acc[4][4];
#pragma unroll
    for (int r = 0; r < 4; ++r)
#pragma unroll
        for (int o = 0; o < 4; ++o) acc[r][o] = 0.0f;

    // ---- prefetch chunk 0 into registers ----
    float4 xv = *reinterpret_cast<const float4*>(xrow + ih);
    float  wv[9];
    {
        const float* wb = g_W2;        // chunk 0 base
#pragma unroll
        for (int s = 0; s < 9; ++s) wv[s] = wb[t + B_THREADS * s];
    }

    for (int c = 0; c < B_NCHUNK; ++c) {
        // ---- fill smem from prefetched registers ----
        {
            float xs[4] = {xv.x, xv.y, xv.z, xv.w};
#pragma unroll
            for (int c4 = 0; c4 < 4; ++c4) {
                float xt  = tanhf(xs[c4]);
                int   kb  = (ih + c4) * B_J_DIM;
                float tm2 = 1.0f;
                float tm1 = 2.0f * xt;
                Ts[kb + 0][row] = tm2;
                Ts[kb + 1][row] = tm1;
#pragma unroll
                for (int n = 2; n <= 8; ++n) {
                    float tn = 2.0f * xt * tm1 - tm2;
                    Ts[kb + n][row] = tn;
                    tm2 = tm1; tm1 = tn;
                }
            }
            float* wsf = &Ws[0][0];
#pragma unroll
            for (int s = 0; s < 9; ++s) wsf[t + B_THREADS * s] = wv[s];
        }
        __syncthreads();

        // ---- prefetch next chunk (hidden under compute) ----
        if (c + 1 < B_NCHUNK) {
            xv = *reinterpret_cast<const float4*>(xrow + (c + 1) * B_IC + ih);
            const float* wb = g_W2 + (size_t)(c + 1) * B_KC * B_O_DIM;
#pragma unroll
            for (int s = 0; s < 9; ++s) wv[s] = wb[t + B_THREADS * s];
        }

        // ---- compute: 72 k-steps, 16 FMA per step per thread ----
#pragma unroll 8
        for (int k = 0; k < B_KC; ++k) {
            float4 av = *reinterpret_cast<const float4*>(&Ts[k][ty * 4]);
            float4 bv = *reinterpret_cast<const float4*>(&Ws[k][tx * 4]);
            float ar[4] = {av.x, av.y, av.z, av.w};
            float wr[4] = {bv.x, bv.y, bv.z, bv.w};
#pragma unroll
            for (int r = 0; r < 4; ++r)
#pragma unroll
                for (int o = 0; o < 4; ++o)
                    acc[r][o] = fmaf(ar[r], wr[o], acc[r][o]);
        }
        __syncthreads();
    }

    // ---- store: float4 per row, coalesced 128B segments per warp ----
#pragma unroll
    for (int r = 0; r < 4; ++r) {
        float4 v = make_float4(acc[r][0], acc[r][1], acc[r][2], acc[r][3]);
        *reinterpret_cast<float4*>(out + (size_t)(b0 + ty * 4 + r) * B_O_DIM + tx * 4) = v;
    }
}

extern "C" void kernel_launch(void* const* d_in, const int* in_sizes, int n_in,
                              void* d_out, int out_size) {
    const float* x = (const float*)d_in[0];           // [B, 512] f32
    const float* w = (const float*)d_in[1];           // [512, 32, 9] f32
    float* out = (float*)d_out;                        // [B, 32] f32

    int B = in_sizes[0] / B_I_DIM;                     // 65536

    // 1) repack weights to k-major scratch (tiny)
    int wtot = B_I_DIM * B_O_DIM * B_J_DIM;
    repack_w_kernel<<<(wtot + 255) / 256, 256>>>(w);

    // 2) fused tanh + Chebyshev basis + GEMM
    cheby_kan_kernel<<<B / B_TB, B_THREADS>>>(x, out);
}

// round 4
// speedup vs baseline: 4.2826x; 4.2826x over previous
#include <cuda_runtime.h>
#include <cuda_fp16.h>
#include <stdint.h>
#include <math.h>

// Problem constants
#define P_I     512
#define P_O     32
#define P_J     9
#define P_CHI   16                 // inputs per k-chunk
#define P_CHK   144                // dense k per chunk (16*9)
#define P_NCH   32                 // 512/16
#define P_ROWS  128                // batch rows per CTA
#define P_THR   128                // 4 warps, 32 rows each

// smem layout (halves): W [32][152] then basisT [144][136]
#define WPAD    152
#define BPAD    136
#define SM_W    0
#define SM_B    (P_O * WPAD * 2)                   // 9728 bytes
#define SM_TOT  (SM_B + P_CHK * BPAD * 2)          // 48896 bytes (<48KB)

// Repacked fp16 weights, dense-k chunk-major: g_W2[c][o][kl], kl=0..143
__device__ __half g_W2[P_NCH * P_O * P_CHK];

__global__ void repack_kernel(const float* __restrict__ w) {
    int idx = blockIdx.x * blockDim.x + threadIdx.x;
    if (idx >= P_NCH * P_O * P_CHK) return;
    int kl = idx % P_CHK;
    int o  = (idx / P_CHK) % P_O;
    int c  = idx / (P_CHK * P_O);
    int k  = c * P_CHK + kl;
    int i  = k / P_J;
    int j  = k % P_J;
    g_W2[idx] = __float2half(w[(i * P_O + o) * P_J + j]);
}

// ---------------- warp-level MMA primitives (sm_80 baseline ISA) ----------------
__device__ __forceinline__ uint32_t smem_u32(const void* p) {
    uint32_t a;
    asm("{ .reg .u64 t; cvta.to.shared.u64 t, %1; cvt.u32.u64 %0, t; }" : "=r"(a) : "l"(p));
    return a;
}
__device__ __forceinline__ void ldm_x4(uint32_t (&r)[4], uint32_t addr) {
    asm volatile("ldmatrix.sync.aligned.m8n8.x4.shared.b16 {%0,%1,%2,%3}, [%4];"
                 : "=r"(r[0]), "=r"(r[1]), "=r"(r[2]), "=r"(r[3]) : "r"(addr));
}
__device__ __forceinline__ void ldm_x4_t(uint32_t (&r)[4], uint32_t addr) {
    asm volatile("ldmatrix.sync.aligned.m8n8.x4.trans.shared.b16 {%0,%1,%2,%3}, [%4];"
                 : "=r"(r[0]), "=r"(r[1]), "=r"(r[2]), "=r"(r[3]) : "r"(addr));
}
__device__ __forceinline__ void mma16816(float (&d)[4], const uint32_t (&a)[4],
                                         uint32_t b0, uint32_t b1) {
    asm volatile(
        "mma.sync.aligned.m16n8k16.row.col.f32.f16.f16.f32 "
        "{%0,%1,%2,%3}, {%4,%5,%6,%7}, {%8,%9}, {%0,%1,%2,%3};"
        : "+f"(d[0]), "+f"(d[1]), "+f"(d[2]), "+f"(d[3])
        : "r"(a[0]), "r"(a[1]), "r"(a[2]), "r"(a[3]), "r"(b0), "r"(b1));
}
__device__ __forceinline__ uint32_t pack2(float a, float b) {
    __half2 h = __floats2half2_rn(a, b);
    return *reinterpret_cast<uint32_t*>(&h);
}

__global__ __launch_bounds__(P_THR)
void cheby_mma_kernel(const float* __restrict__ x, float* __restrict__ out) {
    extern __shared__ char smem[];
    const uint32_t sW = smem_u32(smem) + SM_W;
    const uint32_t sB = smem_u32(smem) + SM_B;
    __half* smW = reinterpret_cast<__half*>(smem + SM_W);

    const int t    = threadIdx.x;
    const int lane = t & 31;
    const int w    = t >> 5;           // warp id: rows [32w, 32w+32)
    const int b0   = blockIdx.x * P_ROWS;

    // generation mapping: thread owns row-pair (2rp, 2rp+1), 8 inputs (ig half)
    const int rp = t & 63;
    const int ig = t >> 6;

    // ldmatrix per-lane address components
    const int g = lane >> 3, l = lane & 7;
    // W fragments (non-trans): groups -> (oRow, kHalf)
    const int oRow = (g & 1) * 8 + l;
    const int kHlf = (g >> 1) * 8;
    const uint32_t wAddrBase = sW + (uint32_t)(oRow * WPAD + kHlf) * 2u;
    // basis fragments (trans): groups -> (kOff, mOff)
    const int kOff = (g >> 1) * 8 + l;
    const int mOff = (g & 1) * 8;
    const uint32_t bAddrBase = sB + (uint32_t)(kOff * BPAD + w * 32 + mOff) * 2u;

    float acc[2][4][4];
#pragma unroll
    for (int ot = 0; ot < 2; ++ot)
#pragma unroll
        for (int rt = 0; rt < 4; ++rt)
#pragma unroll
            for (int q = 0; q < 4; ++q) acc[ot][rt][q] = 0.0f;

    for (int c = 0; c < P_NCH; ++c) {
        if (c) __syncthreads();        // mma of chunk c-1 done reading smem

        // ---- load W chunk (9216 B) to smem ----
        {
            const __half* wp = g_W2 + (size_t)c * (P_O * P_CHK);
#pragma unroll
            for (int q = 0; q < 5; ++q) {
                int idx = t + P_THR * q;             // 576 uint4 blocks
                if (idx < (P_O * P_CHK) / 8) {
                    int o = idx / 18, s = idx % 18;  // 18 x 8 halves per o-row
                    uint4 v = *reinterpret_cast<const uint4*>(wp + o * P_CHK + s * 8);
                    *reinterpret_cast<uint4*>(smW + o * WPAD + s * 8) = v;
                }
            }
        }

        // ---- generate basis tile: basisT[i_local*9+j][row], half2 per row-pair ----
        {
            const float* xp = x + (size_t)(b0 + 2 * rp) * P_I + c * P_CHI + ig * 8;
            float xr0[8], xr1[8];
            *reinterpret_cast<float4*>(&xr0[0]) = *reinterpret_cast<const float4*>(xp);
            *reinterpret_cast<float4*>(&xr0[4]) = *reinterpret_cast<const float4*>(xp + 4);
            *reinterpret_cast<float4*>(&xr1[0]) = *reinterpret_cast<const float4*>(xp + P_I);
            *reinterpret_cast<float4*>(&xr1[4]) = *reinterpret_cast<const float4*>(xp + P_I + 4);
#pragma unroll
            for (int p = 0; p < 8; ++p) {
                float t0 = tanhf(xr0[p]);
                float t1 = tanhf(xr1[p]);
                float x20 = t0 + t0, x21 = t1 + t1;
                uint32_t base = sB + (uint32_t)(((ig * 8 + p) * P_J) * BPAD + 2 * rp) * 2u;
                float a0 = 1.0f, b0v = 1.0f;      // U0
                float a1 = x20, b1v = x21;        // U1
                asm volatile("st.shared.b32 [%0], %1;" :: "r"(base), "r"(pack2(a0, b0v)));
                asm volatile("st.shared.b32 [%0], %1;" :: "r"(base + BPAD * 2), "r"(pack2(a1, b1v)));
#pragma unroll
                for (int j = 2; j <= 8; ++j) {
                    float a2 = fmaf(x20, a1, -a0);
                    float b2 = fmaf(x21, b1v, -b0v);
                    asm volatile("st.shared.b32 [%0], %1;"
                                 :: "r"(base + (uint32_t)(j * BPAD * 2)), "r"(pack2(a2, b2)));
                    a0 = a1; a1 = a2; b0v = b1v; b1v = b2;
                }
            }
        }
        __syncthreads();

        // ---- MMA over 9 k-steps of 16 ----
        uint32_t wAddr = wAddrBase;
        uint32_t bAddr = bAddrBase;
#pragma unroll
        for (int ks = 0; ks < 9; ++ks) {
            uint32_t aW0[4], aW1[4], bb0[4], bb1[4];
            ldm_x4(aW0, wAddr);                          // o 0..15
            ldm_x4(aW1, wAddr + 16u * WPAD * 2u);        // o 16..31
            ldm_x4_t(bb0, bAddr);                        // rows m0..m0+15
            ldm_x4_t(bb1, bAddr + 32u);                  // rows m0+16..m0+31
            // row-tile rt: 0:(bb0[0],bb0[2]) 1:(bb0[1],bb0[3]) 2:(bb1[0],bb1[2]) 3:(bb1[1],bb1[3])
            mma16816(acc[0][0], aW0, bb0[0], bb0[2]);
            mma16816(acc[1][0], aW1, bb0[0], bb0[2]);
            mma16816(acc[0][1], aW0, bb0[1], bb0[3]);
            mma16816(acc[1][1], aW1, bb0[1], bb0[3]);
            mma16816(acc[0][2], aW0, bb1[0], bb1[2]);
            mma16816(acc[1][2], aW1, bb1[0], bb1[2]);
            mma16816(acc[0][3], aW0, bb1[1], bb1[3]);
            mma16816(acc[1][3], aW1, bb1[1], bb1[3]);
            wAddr += 32u;                  // +16 halves along k
            bAddr += 16u * BPAD * 2u;      // +16 k-rows
        }
    }

    // ---- epilogue: C fragment -> gmem ----
    const int qr = lane >> 2;            // m-row within tile (= output o low 3 bits)
    const int qc = (lane & 3) * 2;       // n-col within tile (= batch row pair)
#pragma unroll
    for (int rt = 0; rt < 4; ++rt) {
        int r = b0 + 32 * w + 8 * rt + qc;
        float* po0 = out + (size_t)r * P_O;
        float* po1 = out + (size_t)(r + 1) * P_O;
#pragma unroll
        for (int ot = 0; ot < 2; ++ot) {
            int o = ot * 16 + qr;
            po0[o]     = acc[ot][rt][0];
            po1[o]     = acc[ot][rt][1];
            po0[o + 8] = acc[ot][rt][2];
            po1[o + 8] = acc[ot][rt][3];
        }
    }
}

extern "C" void kernel_launch(void* const* d_in, const int* in_sizes, int n_in,
                              void* d_out, int out_size) {
    const float* x = (const float*)d_in[0];      // [65536, 512] f32
    const float* wc = (const float*)d_in[1];     // [512, 32, 9] f32
    float* out = (float*)d_out;                  // [65536, 32] f32

    int Brows = in_sizes[0] / P_I;

    int wtot = P_NCH * P_O * P_CHK;              // 147456
    repack_kernel<<<(wtot + 255) / 256, 256>>>(wc);

    cheby_mma_kernel<<<Brows / P_ROWS, P_THR, SM_TOT>>>(x, out);
}